// round 3
// baseline (speedup 1.0000x reference)
#include <cuda_runtime.h>
#include <cstdint>
#include <cstddef>

typedef unsigned long long ull;

#define B_ 128
#define I_ 64
#define S_ 2048
#define H_ 128
#define O_ 64
#define G4_ 512  // 4*H

// ---------------- scratch (allocation-free: device globals) ----------------
// x transposed: [t][bg(16)][bb(8)][i(64)]
__device__ float g_xT[(size_t)S_ * 16 * 8 * I_];
// hidden states: [b][t][h]
__device__ float g_hs[(size_t)B_ * S_ * H_];

// ---------------- PTX helpers ----------------
__device__ __forceinline__ void ffma2(ull& acc, ull a, ull b) {
    asm volatile("fma.rn.f32x2 %0, %1, %2, %0;" : "+l"(acc) : "l"(a), "l"(b));
}
__device__ __forceinline__ ull fadd2(ull a, ull b) {
    ull r; asm("add.rn.f32x2 %0, %1, %2;" : "=l"(r) : "l"(a), "l"(b)); return r;
}
__device__ __forceinline__ ull splat2(float w) {
    ull r; asm("mov.b64 %0, {%1, %1};" : "=l"(r) : "f"(w)); return r;
}
__device__ __forceinline__ float2 u2f(ull v) {
    float2 f; asm("mov.b64 {%0, %1}, %2;" : "=f"(f.x), "=f"(f.y) : "l"(v)); return f;
}
__device__ __forceinline__ ull f2u(float2 f) {
    ull v; asm("mov.b64 %0, {%1, %2};" : "=l"(v) : "f"(f.x), "f"(f.y)); return v;
}
__device__ __forceinline__ uint32_t smem_u32(const void* p) {
    return (uint32_t)__cvta_generic_to_shared(p);
}
__device__ __forceinline__ uint32_t mapa_rank(uint32_t addr, uint32_t rank) {
    uint32_t r;
    asm("mapa.shared::cluster.u32 %0, %1, %2;" : "=r"(r) : "r"(addr), "r"(rank));
    return r;
}
__device__ __forceinline__ void st_cluster_u64(uint32_t addr, ull v) {
    asm volatile("st.shared::cluster.u64 [%0], %1;" :: "r"(addr), "l"(v) : "memory");
}
__device__ __forceinline__ void cluster_sync_all() {
    asm volatile("barrier.cluster.arrive.aligned;" ::: "memory");
    asm volatile("barrier.cluster.wait.aligned;"   ::: "memory");
}
__device__ __forceinline__ float sigf(float x) {
    return __fdividef(1.0f, 1.0f + __expf(-x));
}
__device__ __forceinline__ float tanhf_(float x) {
    float e = __expf(2.0f * x);               // +inf for large x -> 1; 0 for very neg -> -1
    return 1.0f - __fdividef(2.0f, e + 1.0f);
}

// ---------------- transpose: x (B, I, S) -> g_xT [t][bg][bb][i] ----------------
__global__ void __launch_bounds__(256) transpose_kernel(const float* __restrict__ x) {
    __shared__ float tile[32][33];
    int tx = threadIdx.x, ty = threadIdx.y;
    int t0 = blockIdx.x * 32;       // time tile
    int r0 = blockIdx.y * 32;       // r = b*64 + i tile
#pragma unroll
    for (int j = 0; j < 32; j += 8)
        tile[ty + j][tx] = x[(size_t)(r0 + ty + j) * S_ + (t0 + tx)];
    __syncthreads();
#pragma unroll
    for (int j = 0; j < 32; j += 8) {
        int t = t0 + ty + j;
        int r = r0 + tx;
        int b = r >> 6, i = r & 63;
        g_xT[(((size_t)t * 16 + (b >> 3)) * 8 + (b & 7)) * 64 + i] = tile[tx][ty + j];
    }
}

// ---------------- persistent cluster scan ----------------
struct ScanSM {
    float Wout[192][64];   // k<64: Wx_out ; k>=64: Wh_out    (48KB)
    float Win[256][64];    // k<128: Wx_in ; k>=128: Wh_in    (64KB)
    float actA[192][8];    // k<64: xt ; k>=64: h             (6KB)
    float actB[256][8];    // k<128: x_in ; k>=128: h_in      (8KB)
    ull   red[8][64][4];   // per-warp GEMM partials          (16KB)
    ull   gbuf[64][4];     // reduced gates                   (2KB)
    ull   xbuf[16][4];     // x_in slice
    ull   hbuf[16][4];     // h_in slice
    ull   h2buf[16][4];    // h slice
    float bo[64];
    float bi[64];
};

__global__ void __launch_bounds__(256, 1) __cluster_dims__(8, 1, 1)
scan_kernel(const float* __restrict__ Wx_out, const float* __restrict__ Wh_out,
            const float* __restrict__ b_out,
            const float* __restrict__ Wx_in, const float* __restrict__ Wh_in,
            const float* __restrict__ b_in)
{
    extern __shared__ char smraw[];
    ScanSM& sm = *reinterpret_cast<ScanSM*>(smraw);

    const int tid  = threadIdx.x;
    const int rank = blockIdx.x & 7;    // CTA rank within cluster (owns hidden cols rank*16..+16)
    const int bg   = blockIdx.x >> 3;   // batch group (8 batches)

    // ---- load weight slices: local col lc -> global gate col gc
    for (int idx = tid; idx < 192 * 64; idx += 256) {
        int k = idx >> 6, lc = idx & 63;
        int gc = ((lc >> 4) << 7) + (rank << 4) + (lc & 15);
        sm.Wout[k][lc] = (k < 64) ? Wx_out[k * G4_ + gc] : Wh_out[(k - 64) * G4_ + gc];
    }
    for (int idx = tid; idx < 256 * 64; idx += 256) {
        int k = idx >> 6, lc = idx & 63;
        int gc = ((lc >> 4) << 7) + (rank << 4) + (lc & 15);
        sm.Win[k][lc] = (k < 128) ? Wx_in[k * G4_ + gc] : Wh_in[(k - 128) * G4_ + gc];
    }
    if (tid < 64) {
        int gc = ((tid >> 4) << 7) + (rank << 4) + (tid & 15);
        sm.bo[tid] = b_out[gc];
        sm.bi[tid] = b_in[gc];
    }
    // ---- init actA: xt(0) + h = 0
    {
        int bb = tid >> 6, i = tid & 63;
        size_t base = (size_t)bg * 8;   // t = 0
        sm.actA[i][bb]     = g_xT[(base + bb) * 64 + i];
        sm.actA[i][bb + 4] = g_xT[(base + bb + 4) * 64 + i];
    }
    for (int idx = tid; idx < 128 * 8; idx += 256)
        sm.actA[64 + (idx >> 3)][idx & 7] = 0.0f;

    ull cO = 0, cN = 0, oG = 0;  // outer cell, inner cell, o-gate (threads < 64)

    const int w    = tid >> 5;
    const int lane = tid & 31;
    const int cq   = lane & 15;   // column quad (4 cols)
    const int bh   = lane >> 4;   // batch half (4 batches)

    __syncthreads();
    cluster_sync_all();

#pragma unroll 1
    for (int t = 0; t < S_; ++t) {
        // ================= PHASE A: outer gates =================
        ull acc[4][2];
#pragma unroll
        for (int j = 0; j < 4; ++j) { acc[j][0] = 0; acc[j][1] = 0; }
        {
            const float* wp = &sm.Wout[w * 24][cq * 4];
            const float* ap = &sm.actA[w * 24][bh * 4];
#pragma unroll 4
            for (int k = 0; k < 24; ++k) {
                float4 wv = *reinterpret_cast<const float4*>(wp); wp += 64;
                ulonglong2 av = *reinterpret_cast<const ulonglong2*>(ap); ap += 8;
                ull w0 = splat2(wv.x), w1 = splat2(wv.y), w2 = splat2(wv.z), w3 = splat2(wv.w);
                ffma2(acc[0][0], w0, av.x); ffma2(acc[0][1], w0, av.y);
                ffma2(acc[1][0], w1, av.x); ffma2(acc[1][1], w1, av.y);
                ffma2(acc[2][0], w2, av.x); ffma2(acc[2][1], w2, av.y);
                ffma2(acc[3][0], w3, av.x); ffma2(acc[3][1], w3, av.y);
            }
        }
#pragma unroll
        for (int j = 0; j < 4; ++j) {
            ulonglong2 v; v.x = acc[j][0]; v.y = acc[j][1];
            *reinterpret_cast<ulonglong2*>(&sm.red[w][cq * 4 + j][bh * 2]) = v;
        }
        __syncthreads();
        {   // reduce 8 warp-partials + bias
            int lc = tid >> 2, pr = tid & 3;
            ull s = splat2(sm.bo[lc]);
#pragma unroll
            for (int ww = 0; ww < 8; ++ww) s = fadd2(s, sm.red[ww][lc][pr]);
            sm.gbuf[lc][pr] = s;
        }
        __syncthreads();
        if (tid < 64) {  // nonlinearity A
            int c = tid & 15, pr = tid >> 4;
            float2 iv = u2f(sm.gbuf[c][pr]);
            float2 fv = u2f(sm.gbuf[16 + c][pr]);
            float2 ov = u2f(sm.gbuf[32 + c][pr]);
            float2 gv = u2f(sm.gbuf[48 + c][pr]);
            iv.x = sigf(iv.x);   iv.y = sigf(iv.y);
            fv.x = sigf(fv.x);   fv.y = sigf(fv.y);
            ov.x = sigf(ov.x);   ov.y = sigf(ov.y);
            gv.x = tanhf_(gv.x); gv.y = tanhf_(gv.y);
            float2 cf = u2f(cO);
            float2 xin; xin.x = iv.x * gv.x; xin.y = iv.y * gv.y;
            float2 hin; hin.x = fv.x * cf.x; hin.y = fv.y * cf.y;
            oG = f2u(ov);
            sm.xbuf[c][pr] = f2u(xin);
            sm.hbuf[c][pr] = f2u(hin);
        }
        __syncthreads();
        {   // push x_in / h_in slice to all 8 CTAs' actB
            int e = tid & 127;
            int c = e & 15, pr = (e >> 4) & 3, which = e >> 6;
            ull v = which ? sm.hbuf[c][pr] : sm.xbuf[c][pr];
            uint32_t off = (uint32_t)((((which << 7) + (rank << 4) + c) * 32) + pr * 8);
            uint32_t local = smem_u32(&sm.actB[0][0]) + off;
            int rb = (tid >> 7) * 4;
#pragma unroll
            for (int rr = 0; rr < 4; ++rr)
                st_cluster_u64(mapa_rank(local, (uint32_t)(rb + rr)), v);
        }
        // prefetch xt(t+1)
        float x0 = 0.0f, x1 = 0.0f;
        if (t + 1 < S_) {
            int bb = tid >> 6, i = tid & 63;
            size_t base = ((size_t)(t + 1) * 16 + bg) * 8;
            x0 = g_xT[(base + bb) * 64 + i];
            x1 = g_xT[(base + bb + 4) * 64 + i];
        }
        cluster_sync_all();   // sync1: actB complete cluster-wide

        // ================= PHASE B: inner gates =================
#pragma unroll
        for (int j = 0; j < 4; ++j) { acc[j][0] = 0; acc[j][1] = 0; }
        {
            const float* wp = &sm.Win[w * 32][cq * 4];
            const float* ap = &sm.actB[w * 32][bh * 4];
#pragma unroll 4
            for (int k = 0; k < 32; ++k) {
                float4 wv = *reinterpret_cast<const float4*>(wp); wp += 64;
                ulonglong2 av = *reinterpret_cast<const ulonglong2*>(ap); ap += 8;
                ull w0 = splat2(wv.x), w1 = splat2(wv.y), w2 = splat2(wv.z), w3 = splat2(wv.w);
                ffma2(acc[0][0], w0, av.x); ffma2(acc[0][1], w0, av.y);
                ffma2(acc[1][0], w1, av.x); ffma2(acc[1][1], w1, av.y);
                ffma2(acc[2][0], w2, av.x); ffma2(acc[2][1], w2, av.y);
                ffma2(acc[3][0], w3, av.x); ffma2(acc[3][1], w3, av.y);
            }
        }
#pragma unroll
        for (int j = 0; j < 4; ++j) {
            ulonglong2 v; v.x = acc[j][0]; v.y = acc[j][1];
            *reinterpret_cast<ulonglong2*>(&sm.red[w][cq * 4 + j][bh * 2]) = v;
        }
        __syncthreads();
        {
            int lc = tid >> 2, pr = tid & 3;
            ull s = splat2(sm.bi[lc]);
#pragma unroll
            for (int ww = 0; ww < 8; ++ww) s = fadd2(s, sm.red[ww][lc][pr]);
            sm.gbuf[lc][pr] = s;
        }
        __syncthreads();
        if (tid < 64) {  // nonlinearity B + state update + output store
            int c = tid & 15, pr = tid >> 4;
            float2 ii = u2f(sm.gbuf[c][pr]);
            float2 fi = u2f(sm.gbuf[16 + c][pr]);
            float2 oi = u2f(sm.gbuf[32 + c][pr]);
            float2 gg = u2f(sm.gbuf[48 + c][pr]);
            ii.x = sigf(ii.x);   ii.y = sigf(ii.y);
            fi.x = sigf(fi.x);   fi.y = sigf(fi.y);
            oi.x = sigf(oi.x);   oi.y = sigf(oi.y);
            gg.x = tanhf_(gg.x); gg.y = tanhf_(gg.y);
            float2 cn = u2f(cN);
            cn.x = fi.x * cn.x + ii.x * gg.x;
            cn.y = fi.y * cn.y + ii.y * gg.y;
            float2 co;
            co.x = oi.x * tanhf_(cn.x);
            co.y = oi.y * tanhf_(cn.y);
            float2 ovv = u2f(oG);
            float2 h;
            h.x = ovv.x * tanhf_(co.x);
            h.y = ovv.y * tanhf_(co.y);
            cN = f2u(cn); cO = f2u(co);
            sm.h2buf[c][pr] = f2u(h);
            int b0 = bg * 8 + pr * 2;
            size_t a0 = ((size_t)b0 * S_ + t) * H_ + (rank << 4) + c;
            g_hs[a0] = h.x;
            g_hs[a0 + (size_t)S_ * H_] = h.y;
        }
        __syncthreads();
        {   // push h slice to all 8 CTAs' actA (h region)
            int e = tid & 63;
            int c = e & 15, pr = e >> 4;
            ull v = sm.h2buf[c][pr];
            uint32_t off = (uint32_t)(((64 + (rank << 4) + c) * 32) + pr * 8);
            uint32_t local = smem_u32(&sm.actA[0][0]) + off;
            int rb = (tid >> 6) * 2;
            st_cluster_u64(mapa_rank(local, (uint32_t)rb), v);
            st_cluster_u64(mapa_rank(local, (uint32_t)(rb + 1)), v);
        }
        if (t + 1 < S_) {  // store prefetched xt(t+1)
            int bb = tid >> 6, i = tid & 63;
            sm.actA[i][bb]     = x0;
            sm.actA[i][bb + 4] = x1;
        }
        cluster_sync_all();   // sync2: actA (h + xt) complete cluster-wide
    }
}

// ---------------- final projection: out = hs @ W_lin^T + b_lin ----------------
struct ProjSM {
    float Wt[128][66];     // W_lin transposed, padded (33.8KB)
    float hsS[64][128];    // 64-row hs tile (32KB)
};

__global__ void __launch_bounds__(256, 1)
proj_kernel(const float* __restrict__ W_lin, const float* __restrict__ b_lin,
            float* __restrict__ out)
{
    extern __shared__ char smraw[];
    ProjSM& sm = *reinterpret_cast<ProjSM*>(smraw);
    const int tid = threadIdx.x;
    const size_t row0 = (size_t)blockIdx.x * 64;

    for (int idx = tid; idx < 64 * 128; idx += 256) {
        int oc = idx >> 7, k = idx & 127;
        sm.Wt[k][oc] = W_lin[oc * H_ + k];
    }
    for (int idx = tid; idx < 64 * 128; idx += 256) {
        int rl = idx >> 7, k = idx & 127;
        sm.hsS[rl][k] = g_hs[(row0 + rl) * H_ + k];
    }
    __syncthreads();

    const int cp = tid & 31;   // column pair
    const int rg = tid >> 5;   // row group (8 rows)
    ull acc[8];
#pragma unroll
    for (int rr = 0; rr < 8; ++rr) acc[rr] = 0;

#pragma unroll 4
    for (int k = 0; k < 128; ++k) {
        ull w2 = *reinterpret_cast<const ull*>(&sm.Wt[k][cp * 2]);
#pragma unroll
        for (int rr = 0; rr < 8; ++rr) {
            ull a = splat2(sm.hsS[rg * 8 + rr][k]);
            ffma2(acc[rr], w2, a);
        }
    }
    ull b2 = f2u(make_float2(b_lin[cp * 2], b_lin[cp * 2 + 1]));
#pragma unroll
    for (int rr = 0; rr < 8; ++rr) {
        ull r = fadd2(acc[rr], b2);
        *reinterpret_cast<ull*>(&out[(row0 + rg * 8 + rr) * O_ + cp * 2]) = r;
    }
}

// ---------------- host launcher ----------------
extern "C" void kernel_launch(void* const* d_in, const int* in_sizes, int n_in,
                              void* d_out, int out_size) {
    const float* x      = (const float*)d_in[0];
    const float* Wx_out = (const float*)d_in[1];
    const float* Wh_out = (const float*)d_in[2];
    const float* b_out  = (const float*)d_in[3];
    const float* Wx_in  = (const float*)d_in[4];
    const float* Wh_in  = (const float*)d_in[5];
    const float* b_in   = (const float*)d_in[6];
    const float* W_lin  = (const float*)d_in[7];
    const float* b_lin  = (const float*)d_in[8];
    float* out = (float*)d_out;

    cudaFuncSetAttribute(scan_kernel, cudaFuncAttributeMaxDynamicSharedMemorySize,
                         (int)sizeof(ScanSM));
    cudaFuncSetAttribute(proj_kernel, cudaFuncAttributeMaxDynamicSharedMemorySize,
                         (int)sizeof(ProjSM));

    transpose_kernel<<<dim3(S_ / 32, (B_ * I_) / 32), dim3(32, 8)>>>(x);
    scan_kernel<<<128, 256, sizeof(ScanSM)>>>(Wx_out, Wh_out, b_out, Wx_in, Wh_in, b_in);
    proj_kernel<<<(B_ * S_) / 64, 256, sizeof(ProjSM)>>>(W_lin, b_lin, out);
}

// round 7
// speedup vs baseline: 1.0007x; 1.0007x over previous
#include <cuda_runtime.h>
#include <cstdint>
#include <cstddef>

typedef unsigned long long ull;

#define B_ 128
#define I_ 64
#define S_ 2048
#define H_ 128
#define O_ 64
#define G4_ 512  // 4*H

// ---------------- scratch (allocation-free: device globals) ----------------
// x transposed: [t][bg(16)][bb(8)][i(64)]
__device__ float g_xT[(size_t)S_ * 16 * 8 * I_];
// hidden states: [b][t][h]
__device__ float g_hs[(size_t)B_ * S_ * H_];

// ---------------- PTX helpers ----------------
__device__ __forceinline__ void ffma2(ull& acc, ull a, ull b) {
    asm volatile("fma.rn.f32x2 %0, %1, %2, %0;" : "+l"(acc) : "l"(a), "l"(b));
}
__device__ __forceinline__ ull fadd2(ull a, ull b) {
    ull r; asm("add.rn.f32x2 %0, %1, %2;" : "=l"(r) : "l"(a), "l"(b)); return r;
}
__device__ __forceinline__ ull splat2(float w) {
    ull r; asm("mov.b64 %0, {%1, %1};" : "=l"(r) : "f"(w)); return r;
}
__device__ __forceinline__ float2 u2f(ull v) {
    float2 f; asm("mov.b64 {%0, %1}, %2;" : "=f"(f.x), "=f"(f.y) : "l"(v)); return f;
}
__device__ __forceinline__ ull f2u(float2 f) {
    ull v; asm("mov.b64 %0, {%1, %2};" : "=l"(v) : "f"(f.x), "f"(f.y)); return v;
}
__device__ __forceinline__ uint32_t smem_u32(const void* p) {
    return (uint32_t)__cvta_generic_to_shared(p);
}
__device__ __forceinline__ uint32_t mapa_rank(uint32_t addr, uint32_t rank) {
    uint32_t r;
    asm("mapa.shared::cluster.u32 %0, %1, %2;" : "=r"(r) : "r"(addr), "r"(rank));
    return r;
}
__device__ __forceinline__ void st_cluster_u64(uint32_t addr, ull v) {
    asm volatile("st.shared::cluster.u64 [%0], %1;" :: "r"(addr), "l"(v) : "memory");
}
__device__ __forceinline__ void cluster_sync_all() {
    asm volatile("barrier.cluster.arrive.aligned;" ::: "memory");
    asm volatile("barrier.cluster.wait.aligned;"   ::: "memory");
}
__device__ __forceinline__ float sigf(float x) {
    return __fdividef(1.0f, 1.0f + __expf(-x));
}
__device__ __forceinline__ float tanhf_(float x) {
    float e = __expf(2.0f * x);               // +inf for large x -> 1; 0 for very neg -> -1
    return 1.0f - __fdividef(2.0f, e + 1.0f);
}

// ---------------- transpose: x (B, I, S) -> g_xT [t][bg][bb][i] ----------------
__global__ void __launch_bounds__(256) transpose_kernel(const float* __restrict__ x) {
    __shared__ float tile[32][33];
    int tx = threadIdx.x, ty = threadIdx.y;
    int t0 = blockIdx.x * 32;       // time tile
    int r0 = blockIdx.y * 32;       // r = b*64 + i tile
#pragma unroll
    for (int j = 0; j < 32; j += 8)
        tile[ty + j][tx] = x[(size_t)(r0 + ty + j) * S_ + (t0 + tx)];
    __syncthreads();
#pragma unroll
    for (int j = 0; j < 32; j += 8) {
        int t = t0 + ty + j;
        int r = r0 + tx;
        int b = r >> 6, i = r & 63;
        g_xT[(((size_t)t * 16 + (b >> 3)) * 8 + (b & 7)) * 64 + i] = tile[tx][ty + j];
    }
}

// ---------------- persistent cluster scan ----------------
struct ScanSM {
    float Wout[192][64];   // k<64: Wx_out ; k>=64: Wh_out    (48KB)
    float Win[256][64];    // k<128: Wx_in ; k>=128: Wh_in    (64KB)
    float actA[192][8];    // k<64: xt ; k>=64: h             (6KB)
    float actB[256][8];    // k<128: x_in ; k>=128: h_in      (8KB)
    ull   red[8][64][4];   // per-warp GEMM partials          (16KB)
    ull   gbuf[64][4];     // reduced gates                   (2KB)
    ull   xbuf[16][4];     // x_in slice
    ull   hbuf[16][4];     // h_in slice
    ull   h2buf[16][4];    // h slice
    float bo[64];
    float bi[64];
};

__global__ void __launch_bounds__(256, 1) __cluster_dims__(8, 1, 1)
scan_kernel(const float* __restrict__ Wx_out, const float* __restrict__ Wh_out,
            const float* __restrict__ b_out,
            const float* __restrict__ Wx_in, const float* __restrict__ Wh_in,
            const float* __restrict__ b_in)
{
    extern __shared__ char smraw[];
    ScanSM& sm = *reinterpret_cast<ScanSM*>(smraw);

    const int tid  = threadIdx.x;
    const int rank = blockIdx.x & 7;    // CTA rank within cluster (owns hidden cols rank*16..+16)
    const int bg   = blockIdx.x >> 3;   // batch group (8 batches)

    // ---- load weight slices: local col lc -> global gate col gc
    for (int idx = tid; idx < 192 * 64; idx += 256) {
        int k = idx >> 6, lc = idx & 63;
        int gc = ((lc >> 4) << 7) + (rank << 4) + (lc & 15);
        sm.Wout[k][lc] = (k < 64) ? Wx_out[k * G4_ + gc] : Wh_out[(k - 64) * G4_ + gc];
    }
    for (int idx = tid; idx < 256 * 64; idx += 256) {
        int k = idx >> 6, lc = idx & 63;
        int gc = ((lc >> 4) << 7) + (rank << 4) + (lc & 15);
        sm.Win[k][lc] = (k < 128) ? Wx_in[k * G4_ + gc] : Wh_in[(k - 128) * G4_ + gc];
    }
    if (tid < 64) {
        int gc = ((tid >> 4) << 7) + (rank << 4) + (tid & 15);
        sm.bo[tid] = b_out[gc];
        sm.bi[tid] = b_in[gc];
    }
    // ---- init actA: xt(0) + h = 0
    {
        int bb = tid >> 6, i = tid & 63;
        size_t base = (size_t)bg * 8;   // t = 0
        sm.actA[i][bb]     = g_xT[(base + bb) * 64 + i];
        sm.actA[i][bb + 4] = g_xT[(base + bb + 4) * 64 + i];
    }
    for (int idx = tid; idx < 128 * 8; idx += 256)
        sm.actA[64 + (idx >> 3)][idx & 7] = 0.0f;

    ull cO = 0, cN = 0, oG = 0;  // outer cell, inner cell, o-gate (threads < 64)

    const int w    = tid >> 5;
    const int lane = tid & 31;
    const int cq   = lane & 15;   // column quad (4 cols)
    const int bh   = lane >> 4;   // batch half (4 batches)

    __syncthreads();
    cluster_sync_all();

#pragma unroll 1
    for (int t = 0; t < S_; ++t) {
        // ================= PHASE A: outer gates =================
        ull acc[4][2];
#pragma unroll
        for (int j = 0; j < 4; ++j) { acc[j][0] = 0; acc[j][1] = 0; }
        {
            const float* wp = &sm.Wout[w * 24][cq * 4];
            const float* ap = &sm.actA[w * 24][bh * 4];
#pragma unroll 4
            for (int k = 0; k < 24; ++k) {
                float4 wv = *reinterpret_cast<const float4*>(wp); wp += 64;
                ulonglong2 av = *reinterpret_cast<const ulonglong2*>(ap); ap += 8;
                ull w0 = splat2(wv.x), w1 = splat2(wv.y), w2 = splat2(wv.z), w3 = splat2(wv.w);
                ffma2(acc[0][0], w0, av.x); ffma2(acc[0][1], w0, av.y);
                ffma2(acc[1][0], w1, av.x); ffma2(acc[1][1], w1, av.y);
                ffma2(acc[2][0], w2, av.x); ffma2(acc[2][1], w2, av.y);
                ffma2(acc[3][0], w3, av.x); ffma2(acc[3][1], w3, av.y);
            }
        }
#pragma unroll
        for (int j = 0; j < 4; ++j) {
            ulonglong2 v; v.x = acc[j][0]; v.y = acc[j][1];
            *reinterpret_cast<ulonglong2*>(&sm.red[w][cq * 4 + j][bh * 2]) = v;
        }
        __syncthreads();
        {   // reduce 8 warp-partials + bias
            int lc = tid >> 2, pr = tid & 3;
            ull s = splat2(sm.bo[lc]);
#pragma unroll
            for (int ww = 0; ww < 8; ++ww) s = fadd2(s, sm.red[ww][lc][pr]);
            sm.gbuf[lc][pr] = s;
        }
        __syncthreads();
        if (tid < 64) {  // nonlinearity A
            int c = tid & 15, pr = tid >> 4;
            float2 iv = u2f(sm.gbuf[c][pr]);
            float2 fv = u2f(sm.gbuf[16 + c][pr]);
            float2 ov = u2f(sm.gbuf[32 + c][pr]);
            float2 gv = u2f(sm.gbuf[48 + c][pr]);
            iv.x = sigf(iv.x);   iv.y = sigf(iv.y);
            fv.x = sigf(fv.x);   fv.y = sigf(fv.y);
            ov.x = sigf(ov.x);   ov.y = sigf(ov.y);
            gv.x = tanhf_(gv.x); gv.y = tanhf_(gv.y);
            float2 cf = u2f(cO);
            float2 xin; xin.x = iv.x * gv.x; xin.y = iv.y * gv.y;
            float2 hin; hin.x = fv.x * cf.x; hin.y = fv.y * cf.y;
            oG = f2u(ov);
            sm.xbuf[c][pr] = f2u(xin);
            sm.hbuf[c][pr] = f2u(hin);
        }
        __syncthreads();
        {   // push x_in / h_in slice to all 8 CTAs' actB
            int e = tid & 127;
            int c = e & 15, pr = (e >> 4) & 3, which = e >> 6;
            ull v = which ? sm.hbuf[c][pr] : sm.xbuf[c][pr];
            uint32_t off = (uint32_t)((((which << 7) + (rank << 4) + c) * 32) + pr * 8);
            uint32_t local = smem_u32(&sm.actB[0][0]) + off;
            int rb = (tid >> 7) * 4;
#pragma unroll
            for (int rr = 0; rr < 4; ++rr)
                st_cluster_u64(mapa_rank(local, (uint32_t)(rb + rr)), v);
        }
        // prefetch xt(t+1)
        float x0 = 0.0f, x1 = 0.0f;
        if (t + 1 < S_) {
            int bb = tid >> 6, i = tid & 63;
            size_t base = ((size_t)(t + 1) * 16 + bg) * 8;
            x0 = g_xT[(base + bb) * 64 + i];
            x1 = g_xT[(base + bb + 4) * 64 + i];
        }
        cluster_sync_all();   // sync1: actB complete cluster-wide

        // ================= PHASE B: inner gates =================
#pragma unroll
        for (int j = 0; j < 4; ++j) { acc[j][0] = 0; acc[j][1] = 0; }
        {
            const float* wp = &sm.Win[w * 32][cq * 4];
            const float* ap = &sm.actB[w * 32][bh * 4];
#pragma unroll 4
            for (int k = 0; k < 32; ++k) {
                float4 wv = *reinterpret_cast<const float4*>(wp); wp += 64;
                ulonglong2 av = *reinterpret_cast<const ulonglong2*>(ap); ap += 8;
                ull w0 = splat2(wv.x), w1 = splat2(wv.y), w2 = splat2(wv.z), w3 = splat2(wv.w);
                ffma2(acc[0][0], w0, av.x); ffma2(acc[0][1], w0, av.y);
                ffma2(acc[1][0], w1, av.x); ffma2(acc[1][1], w1, av.y);
                ffma2(acc[2][0], w2, av.x); ffma2(acc[2][1], w2, av.y);
                ffma2(acc[3][0], w3, av.x); ffma2(acc[3][1], w3, av.y);
            }
        }
#pragma unroll
        for (int j = 0; j < 4; ++j) {
            ulonglong2 v; v.x = acc[j][0]; v.y = acc[j][1];
            *reinterpret_cast<ulonglong2*>(&sm.red[w][cq * 4 + j][bh * 2]) = v;
        }
        __syncthreads();
        {
            int lc = tid >> 2, pr = tid & 3;
            ull s = splat2(sm.bi[lc]);
#pragma unroll
            for (int ww = 0; ww < 8; ++ww) s = fadd2(s, sm.red[ww][lc][pr]);
            sm.gbuf[lc][pr] = s;
        }
        __syncthreads();
        if (tid < 64) {  // nonlinearity B + state update + output store
            int c = tid & 15, pr = tid >> 4;
            float2 ii = u2f(sm.gbuf[c][pr]);
            float2 fi = u2f(sm.gbuf[16 + c][pr]);
            float2 oi = u2f(sm.gbuf[32 + c][pr]);
            float2 gg = u2f(sm.gbuf[48 + c][pr]);
            ii.x = sigf(ii.x);   ii.y = sigf(ii.y);
            fi.x = sigf(fi.x);   fi.y = sigf(fi.y);
            oi.x = sigf(oi.x);   oi.y = sigf(oi.y);
            gg.x = tanhf_(gg.x); gg.y = tanhf_(gg.y);
            float2 cn = u2f(cN);
            cn.x = fi.x * cn.x + ii.x * gg.x;
            cn.y = fi.y * cn.y + ii.y * gg.y;
            float2 co;
            co.x = oi.x * tanhf_(cn.x);
            co.y = oi.y * tanhf_(cn.y);
            float2 ovv = u2f(oG);
            float2 h;
            h.x = ovv.x * tanhf_(co.x);
            h.y = ovv.y * tanhf_(co.y);
            cN = f2u(cn); cO = f2u(co);
            sm.h2buf[c][pr] = f2u(h);
            int b0 = bg * 8 + pr * 2;
            size_t a0 = ((size_t)b0 * S_ + t) * H_ + (rank << 4) + c;
            g_hs[a0] = h.x;
            g_hs[a0 + (size_t)S_ * H_] = h.y;
        }
        __syncthreads();
        {   // push h slice to all 8 CTAs' actA (h region)
            int e = tid & 63;
            int c = e & 15, pr = e >> 4;
            ull v = sm.h2buf[c][pr];
            uint32_t off = (uint32_t)(((64 + (rank << 4) + c) * 32) + pr * 8);
            uint32_t local = smem_u32(&sm.actA[0][0]) + off;
            int rb = (tid >> 6) * 2;
            st_cluster_u64(mapa_rank(local, (uint32_t)rb), v);
            st_cluster_u64(mapa_rank(local, (uint32_t)(rb + 1)), v);
        }
        if (t + 1 < S_) {  // store prefetched xt(t+1)
            int bb = tid >> 6, i = tid & 63;
            sm.actA[i][bb]     = x0;
            sm.actA[i][bb + 4] = x1;
        }
        cluster_sync_all();   // sync2: actA (h + xt) complete cluster-wide
    }
}

// ---------------- final projection: out = hs @ W_lin^T + b_lin ----------------
struct ProjSM {
    float Wt[128][66];     // W_lin transposed, padded (33.8KB)
    float hsS[64][128];    // 64-row hs tile (32KB)
};

__global__ void __launch_bounds__(256, 1)
proj_kernel(const float* __restrict__ W_lin, const float* __restrict__ b_lin,
            float* __restrict__ out)
{
    extern __shared__ char smraw[];
    ProjSM& sm = *reinterpret_cast<ProjSM*>(smraw);
    const int tid = threadIdx.x;
    const size_t row0 = (size_t)blockIdx.x * 64;

    for (int idx = tid; idx < 64 * 128; idx += 256) {
        int oc = idx >> 7, k = idx & 127;
        sm.Wt[k][oc] = W_lin[oc * H_ + k];
    }
    for (int idx = tid; idx < 64 * 128; idx += 256) {
        int rl = idx >> 7, k = idx & 127;
        sm.hsS[rl][k] = g_hs[(row0 + rl) * H_ + k];
    }
    __syncthreads();

    const int cp = tid & 31;   // column pair
    const int rg = tid >> 5;   // row group (8 rows)
    ull acc[8];
#pragma unroll
    for (int rr = 0; rr < 8; ++rr) acc[rr] = 0;

#pragma unroll 4
    for (int k = 0; k < 128; ++k) {
        ull w2 = *reinterpret_cast<const ull*>(&sm.Wt[k][cp * 2]);
#pragma unroll
        for (int rr = 0; rr < 8; ++rr) {
            ull a = splat2(sm.hsS[rg * 8 + rr][k]);
            ffma2(acc[rr], w2, a);
        }
    }
    ull b2 = f2u(make_float2(b_lin[cp * 2], b_lin[cp * 2 + 1]));
#pragma unroll
    for (int rr = 0; rr < 8; ++rr) {
        ull r = fadd2(acc[rr], b2);
        *reinterpret_cast<ull*>(&out[(row0 + rg * 8 + rr) * O_ + cp * 2]) = r;
    }
}

// ---------------- host launcher ----------------
extern "C" void kernel_launch(void* const* d_in, const int* in_sizes, int n_in,
                              void* d_out, int out_size) {
    const float* x      = (const float*)d_in[0];
    const float* Wx_out = (const float*)d_in[1];
    const float* Wh_out = (const float*)d_in[2];
    const float* b_out  = (const float*)d_in[3];
    const float* Wx_in  = (const float*)d_in[4];
    const float* Wh_in  = (const float*)d_in[5];
    const float* b_in   = (const float*)d_in[6];
    const float* W_lin  = (const float*)d_in[7];
    const float* b_lin  = (const float*)d_in[8];
    float* out = (float*)d_out;

    cudaFuncSetAttribute(scan_kernel, cudaFuncAttributeMaxDynamicSharedMemorySize,
                         (int)sizeof(ScanSM));
    cudaFuncSetAttribute(proj_kernel, cudaFuncAttributeMaxDynamicSharedMemorySize,
                         (int)sizeof(ProjSM));

    transpose_kernel<<<dim3(S_ / 32, (B_ * I_) / 32), dim3(32, 8)>>>(x);
    scan_kernel<<<128, 256, sizeof(ScanSM)>>>(Wx_out, Wh_out, b_out, Wx_in, Wh_in, b_in);
    proj_kernel<<<(B_ * S_) / 64, 256, sizeof(ProjSM)>>>(W_lin, b_lin, out);
}